// round 17
// baseline (speedup 1.0000x reference)
#include <cuda_runtime.h>
#include <cuda_fp16.h>
#include <math.h>
#include <stdint.h>

#define FP16 __half
#define KPAD 384

// ---------------- scratch ----------------
__device__ FP16 g_Rh[512 * 130 * KPAD];   // padded R rows, fp16
__device__ FP16 g_Wh[3 * KPAD * 256];     // W[t][k][f] fp16

static __device__ __forceinline__ uint32_t smem_u32(const void* p) {
    uint32_t r;
    asm("{ .reg .u64 t; cvta.to.shared.u64 t, %1; cvt.u32.u64 %0, t; }" : "=r"(r) : "l"(p));
    return r;
}
static __device__ __forceinline__ void cp16(uint32_t dst, const void* src) {
    asm volatile("cp.async.cg.shared.global [%0], [%1], 16;" :: "r"(dst), "l"(src));
}
static __device__ __forceinline__ void mma_fp16(float* c, const uint32_t* a, uint32_t b0, uint32_t b1) {
    asm volatile(
        "mma.sync.aligned.m16n8k16.row.col.f32.f16.f16.f32 "
        "{%0,%1,%2,%3}, {%4,%5,%6,%7}, {%8,%9}, {%0,%1,%2,%3};"
        : "+f"(c[0]), "+f"(c[1]), "+f"(c[2]), "+f"(c[3])
        : "r"(a[0]), "r"(a[1]), "r"(a[2]), "r"(a[3]), "r"(b0), "r"(b1));
}

// ---------------------------------------------------------------------------
// Kernel A: prep (512 threads) + fused weight split.
// ---------------------------------------------------------------------------
__global__ __launch_bounds__(512) void prep_kernel(
    const int* __restrict__ inputs,
    const int* __restrict__ e1s_, const int* __restrict__ e1e_,
    const int* __restrict__ e2s_, const int* __restrict__ e2e_,
    const int* __restrict__ p1, const int* __restrict__ p2,
    const float* __restrict__ emb,
    const float* __restrict__ pos1, const float* __restrict__ pos2,
    const float* __restrict__ convw)
{
    extern __shared__ float smf[];
    float* we   = smf;                  // [128][101]
    float* emb0 = smf + 12928;
    float* l1   = emb0 + 100;
    float* l2   = l1 + 100;
    float* sc1  = l2 + 100;
    float* sc2  = sc1 + 128;
    float* ine  = sc2 + 128;
    int*   ids  = (int*)(ine + 128);
    int*   q1   = ids + 128;
    int*   q2   = q1 + 128;
    __shared__ float m1s, S1s, m2s, S2s;

    const int b = blockIdx.x;
    const int tid = threadIdx.x;
    const int lane = tid & 31;
    const int wid  = tid >> 5;

    // fused weight split: block b handles flat W elements [b*576, b*576+576)
    {
        int i = b * 576 + tid;
        #pragma unroll
        for (int r = 0; r < 2; ++r, i += 512) {
            if (r == 1 && tid >= 64) break;   // 576 = 512 + 64
            int kk = i >> 8;                  // 0..1151
            int f  = i & 255;
            int t  = (kk * 21846) >> 23;      // kk/384 for kk<1152
            int k  = kk - t * 384;
            float v = (k < 350) ? convw[(size_t)f * 1050 + t * 350 + k] : 0.f;
            g_Wh[(size_t)kk * 256 + f] = __float2half_rn(v);
        }
    }

    if (tid < 128) {
        ids[tid] = inputs[b * 128 + tid];
        q1[tid]  = p1[b * 128 + tid];
        q2[tid]  = p2[b * 128 + tid];
    } else if (tid < 228) {
        emb0[tid - 128] = emb[tid - 128];
    }
    __syncthreads();

    // gather: warp per row (16 warps)
    for (int l = wid; l < 128; l += 16) {
        const float* src = emb + (long long)ids[l] * 100;
        float* dst = we + l * 101;
        #pragma unroll
        for (int d = lane; d < 100; d += 32) dst[d] = src[d];
    }
    __syncthreads();

    if (tid < 100) {
        int s1i = e1s_[b], e1i = e1e_[b];
        int s2i = e2s_[b], e2i = e2e_[b];
        float a = 0.f, c = 0.f;
        for (int l = s1i; l <= e1i; ++l) a += we[l * 101 + tid];
        for (int l = s2i; l <= e2i; ++l) c += we[l * 101 + tid];
        l1[tid] = a / (float)(e1i - s1i + 1);
        l2[tid] = c / (float)(e2i - s2i + 1);
    }
    __syncthreads();

    if (tid < 128) {
        float a = 0.f, c = 0.f;
        const float* w = we + tid * 101;
        #pragma unroll 4
        for (int d = 0; d < 100; ++d) { a += w[d] * l1[d]; c += w[d] * l2[d]; }
        sc1[tid] = a; sc2[tid] = c;
    }
    __syncthreads();

    if (tid < 64) {
        const float* sc = (tid < 32) ? sc1 : sc2;
        int ln = tid & 31;
        float m = -1e30f;
        for (int l = ln; l < 128; l += 32) m = fmaxf(m, sc[l]);
        for (int o = 16; o; o >>= 1) m = fmaxf(m, __shfl_xor_sync(0xffffffffu, m, o));
        float s = 0.f;
        for (int l = ln; l < 128; l += 32) s += __expf(sc[l] - m);
        for (int o = 16; o; o >>= 1) s += __shfl_xor_sync(0xffffffffu, s, o);
        if (ln == 0) {
            if (tid < 32) { m1s = m; S1s = s; } else { m2s = m; S2s = s; }
        }
    }
    __syncthreads();

    if (tid < 128)
        ine[tid] = 0.5f * (__expf(sc1[tid] - m1s) / S1s + __expf(sc2[tid] - m2s) / S2s);
    __syncthreads();

    // R write: warp per row (16 warps), half2 stores, no div/mod
    FP16* rb = g_Rh + ((size_t)b * 130 + 1) * KPAD;
    for (int l = wid; l < 128; l += 16) {
        const float s = ine[l];
        const float sm = (l == 0) ? 0.f : s;
        FP16* row = rb + (size_t)l * KPAD;
        #pragma unroll
        for (int j = 0; j < 3; ++j) {
            int lw = l - 1 + j;
            const float* srcrow = (l != 0 && lw < 128) ? (we + lw * 101) : emb0;
            {
                int p = lane;
                *(__half2*)(row + j * 100 + 2 * p) =
                    __floats2half2_rn(srcrow[2 * p] * sm, srcrow[2 * p + 1] * sm);
            }
            if (lane < 18) {
                int p = 32 + lane;
                *(__half2*)(row + j * 100 + 2 * p) =
                    __floats2half2_rn(srcrow[2 * p] * sm, srcrow[2 * p + 1] * sm);
            }
        }
        if (lane < 25) {
            row[300 + lane] = __float2half_rn(pos1[q1[l] * 25 + lane] * s);
            row[325 + lane] = __float2half_rn(pos2[q2[l] * 25 + lane] * s);
        }
        if (lane < 17) {
            *(__half2*)(row + 350 + 2 * lane) = __floats2half2_rn(0.f, 0.f);
        }
    }
    // zero pad rows 0 and 129
    if (tid < KPAD) {
        FP16 z = __float2half_rn(0.f);
        g_Rh[((size_t)b * 130) * KPAD + tid] = z;
        g_Rh[((size_t)b * 130 + 129) * KPAD + tid] = z;
    }
}

// ---------------------------------------------------------------------------
// Conv fused kernel (R16 proven config, branchless short chunk).
// One CTA per b; 512 thr = 16 warps (4m x 4n), warp tile 32x64, M=128 N=256.
// 18 chunks of k=64 (3 taps x 6); tap-final chunk does only ks 0..1.
// 3 smem buffers, ONE sync per chunk. Fused epilogue: bias+tanh -> Rc_s,
// T=Rc.U, head (2-half online softmax + combine) -> out; WL tail for b<19.
// ---------------------------------------------------------------------------
#define BUFSZ 52224
#define A_STR 144
#define B_STR 528
#define B_OFF  18432
#define CONV_SMEM 162816

static __device__ __forceinline__ void conv_load(uint32_t smb, int t, int kc, int bufi,
                                                 int b, int tid)
{
    const int k0 = kc * 64;
    const uint32_t d = smb + bufi * BUFSZ;
    {
        int am = tid >> 2, ac = (tid & 3) * 16;
        size_t src = ((size_t)(b * 130 + t + am)) * KPAD + k0 + ac;
        uint32_t dst = d + am * A_STR + ac * 2;
        cp16(dst,      g_Rh + src);
        cp16(dst + 16, g_Rh + src + 8);
    }
    {
        int bk = tid >> 3, bn = (tid & 7) * 32;
        size_t src = ((size_t)(t * KPAD + k0 + bk)) * 256 + bn;
        uint32_t dst = d + B_OFF + bk * B_STR + bn * 2;
        cp16(dst,      g_Wh + src);
        cp16(dst + 16, g_Wh + src + 8);
        cp16(dst + 32, g_Wh + src + 16);
        cp16(dst + 48, g_Wh + src + 24);
    }
}

template <int KSN>
static __device__ __forceinline__ void chunk_mma(float acc[2][8][4],
                                                 uint32_t aBase, uint32_t bBase)
{
    #pragma unroll
    for (int ks = 0; ks < KSN; ++ks) {
        uint32_t ah[2][4];
        #pragma unroll
        for (int s = 0; s < 2; ++s) {
            uint32_t addr = aBase + (s * 16) * A_STR + ks * 32;
            asm volatile("ldmatrix.sync.aligned.m8n8.x4.shared.b16 {%0,%1,%2,%3}, [%4];"
                         : "=r"(ah[s][0]), "=r"(ah[s][1]), "=r"(ah[s][2]), "=r"(ah[s][3])
                         : "r"(addr));
        }
        #pragma unroll
        for (int i = 0; i < 4; ++i) {
            uint32_t bb[4];
            uint32_t addr = bBase + (ks * 16) * B_STR + i * 32;
            asm volatile("ldmatrix.sync.aligned.m8n8.x4.trans.shared.b16 {%0,%1,%2,%3}, [%4];"
                         : "=r"(bb[0]), "=r"(bb[1]), "=r"(bb[2]), "=r"(bb[3])
                         : "r"(addr));
            #pragma unroll
            for (int s = 0; s < 2; ++s) {
                mma_fp16(acc[s][2 * i],     ah[s], bb[0], bb[1]);
                mma_fp16(acc[s][2 * i + 1], ah[s], bb[2], bb[3]);
            }
        }
    }
}

__global__ __launch_bounds__(512, 1) void conv_fused_kernel(const float* __restrict__ convb,
                                                            const float* __restrict__ U,
                                                            const float* __restrict__ WL,
                                                            float* __restrict__ out)
{
    extern __shared__ __align__(256) char smc[];
    const uint32_t smb = smem_u32(smc);
    const int tid = threadIdx.x;
    const int lane = tid & 31;
    const int wid  = tid >> 5;
    const int wm = wid & 3;
    const int wn = wid >> 2;
    const int b  = blockIdx.x;

    if (b < 19 && tid < 256) out[512 * 256 + b * 256 + tid] = WL[b * 256 + tid];

    float acc[2][8][4];
    #pragma unroll
    for (int s = 0; s < 2; ++s)
        #pragma unroll
        for (int j = 0; j < 8; ++j)
            #pragma unroll
            for (int x = 0; x < 4; ++x) acc[s][j][x] = 0.f;

    conv_load(smb, 0, 0, 0, b, tid);
    asm volatile("cp.async.commit_group;" ::: "memory");
    conv_load(smb, 0, 1, 1, b, tid);
    asm volatile("cp.async.commit_group;" ::: "memory");

    const uint32_t aAddrBase = smb + (wm * 32 + (lane & 15)) * A_STR + (lane >> 4) * 16;
    const uint32_t bAddrBase = smb + B_OFF + ((lane & 7) + ((lane >> 3) & 1) * 8) * B_STR
                                   + (wn * 64 + (lane >> 4) * 8) * 2;

    int bufi = 0;
    int lt = 0, lkc = 2;   // load cursor: next chunk to load = q+2
    int ct = 0, ckc = 0;   // compute cursor
    for (int q = 0; q < 18; ++q) {
        if (q < 16) asm volatile("cp.async.wait_group 1;" ::: "memory");
        else        asm volatile("cp.async.wait_group 0;" ::: "memory");
        __syncthreads();
        if (q + 2 < 18) {
            int nb = bufi + 2; if (nb >= 3) nb -= 3;
            conv_load(smb, lt, lkc, nb, b, tid);
            asm volatile("cp.async.commit_group;" ::: "memory");
            if (++lkc == 6) { lkc = 0; ++lt; }
        }
        const uint32_t d = bufi * BUFSZ;
        if (ckc == 5) chunk_mma<2>(acc, aAddrBase + d, bAddrBase + d);
        else          chunk_mma<4>(acc, aAddrBase + d, bAddrBase + d);
        if (++ckc == 6) { ckc = 0; ++ct; }
        if (++bufi >= 3) bufi -= 3;
    }
    __syncthreads();

    // ---------------- fused epilogue ----------------
    float* Rc_s = (float*)smc;                 // [128][260]
    float* Us   = (float*)(smc + 133120);      // [256*19]
    float* Ts   = (float*)(smc + 152576);      // [128][20]
    float* Pm   = Us;
    float* Ps   = Us + 256;
    float* Pv   = Us + 512;

    const int col_base = wn * 64 + (lane & 3) * 2;
    #pragma unroll
    for (int s = 0; s < 2; ++s) {
        int row = wm * 32 + s * 16 + (lane >> 2);
        #pragma unroll
        for (int j = 0; j < 8; ++j) {
            int col = col_base + j * 8;
            float b0 = __ldg(convb + col), b1 = __ldg(convb + col + 1);
            Rc_s[row * 260 + col]           = tanhf(acc[s][j][0] + b0);
            Rc_s[row * 260 + col + 1]       = tanhf(acc[s][j][1] + b1);
            Rc_s[(row + 8) * 260 + col]     = tanhf(acc[s][j][2] + b0);
            Rc_s[(row + 8) * 260 + col + 1] = tanhf(acc[s][j][3] + b1);
        }
    }
    for (int i = tid; i < 4864; i += 512) Us[i] = U[i];
    __syncthreads();

    #pragma unroll 1
    for (int r = 0; r < 8; ++r) {
        const int l = wid * 8 + r;
        const float* rcl = Rc_s + l * 260;
        float tac[19];
        #pragma unroll
        for (int c = 0; c < 19; ++c) tac[c] = 0.f;
        #pragma unroll
        for (int i = 0; i < 8; ++i) {
            int f = i * 32 + lane;
            float a = rcl[f];
            const float* up = Us + f * 19;
            #pragma unroll
            for (int c = 0; c < 19; ++c) tac[c] += a * up[c];
        }
        #pragma unroll
        for (int c = 0; c < 19; ++c) {
            float v = tac[c];
            #pragma unroll
            for (int o = 16; o; o >>= 1) v += __shfl_xor_sync(0xffffffffu, v, o);
            if (lane == c) Ts[l * 20 + c] = v;
        }
    }
    __syncthreads();

    const int g = tid & 255;
    const int half = tid >> 8;
    float wl[19];
    #pragma unroll
    for (int c = 0; c < 19; ++c) wl[c] = __ldg(WL + c * 256 + g);

    const int l0 = half * 64;
    float m, S, vmax;
    {
        const float* tl = Ts + l0 * 20;
        float gg = 0.f;
        #pragma unroll
        for (int c = 0; c < 19; ++c) gg += tl[c] * wl[c];
        m = gg; S = 1.f; vmax = Rc_s[l0 * 260 + g];
    }
    for (int l = l0 + 1; l < l0 + 64; ++l) {
        const float* tl = Ts + l * 20;
        float gg = 0.f;
        #pragma unroll
        for (int c = 0; c < 19; ++c) gg += tl[c] * wl[c];
        float rc = Rc_s[l * 260 + g];
        float m2 = fmaxf(m, gg);
        float c1 = __expf(m - m2), c2 = __expf(gg - m2);
        S = S * c1 + c2;
        vmax = fmaxf(vmax * c1, rc * c2);
        m = m2;
    }
    __syncthreads();
    if (half == 1) { Pm[g] = m; Ps[g] = S; Pv[g] = vmax; }
    __syncthreads();
    if (half == 0) {
        float m2 = Pm[g], S2 = Ps[g], v2 = Pv[g];
        float M = fmaxf(m, m2);
        float c1 = __expf(m - M), c2 = __expf(m2 - M);
        float Sc = S * c1 + S2 * c2;
        float V  = fmaxf(vmax * c1, v2 * c2);
        out[(size_t)b * 256 + g] = V / Sc;
    }
}

// ---------------------------------------------------------------------------
extern "C" void kernel_launch(void* const* d_in, const int* in_sizes, int n_in,
                              void* d_out, int out_size)
{
    const int*   inputs = (const int*)d_in[0];
    const int*   e1s    = (const int*)d_in[1];
    const int*   e1e    = (const int*)d_in[2];
    const int*   e2s    = (const int*)d_in[3];
    const int*   e2e    = (const int*)d_in[4];
    const int*   p1     = (const int*)d_in[5];
    const int*   p2     = (const int*)d_in[6];
    const float* emb    = (const float*)d_in[7];
    const float* pos1   = (const float*)d_in[8];
    const float* pos2   = (const float*)d_in[9];
    const float* convw  = (const float*)d_in[10];
    const float* convb  = (const float*)d_in[11];
    const float* U      = (const float*)d_in[12];
    const float* WL     = (const float*)d_in[13];
    float* out = (float*)d_out;

    const int PREP_SMEM = 13996 * 4;
    cudaFuncSetAttribute(prep_kernel, cudaFuncAttributeMaxDynamicSharedMemorySize, PREP_SMEM);
    cudaFuncSetAttribute(conv_fused_kernel, cudaFuncAttributeMaxDynamicSharedMemorySize, CONV_SMEM);

    prep_kernel<<<512, 512, PREP_SMEM>>>(inputs, e1s, e1e, e2s, e2e, p1, p2,
                                         emb, pos1, pos2, convw);
    conv_fused_kernel<<<512, 512, CONV_SMEM>>>(convb, U, WL, out);
}